// round 9
// baseline (speedup 1.0000x reference)
#include <cuda_runtime.h>

// LIF neuron group, T=1000 serial steps x 65536 neurons. Pure HBM stream
// (512 MB read + 256 MB write, irreducible). Converged structure (R5/R6/R8
// all ~6.6 TB/s): float2 lanes, 1024 one-warp blocks (7-vs-6 per SM),
// 8 rotating register buffers x STAGES=5, loads 7 blocks ahead.
// R9 single-variable test: stores switch from .cs (evict-first -> dirty
// lines dribble to DRAM, maximal R/W turnaround) to default write-back
// (dirty data batches in 126MB L2, evicts in long same-direction runs ->
// fewer DRAM bus turnarounds). Loads stay .cs to leave L2 to the writes.

#define NUM_NEURONS 65536
#define T_STEPS     1000
#define NVEC        (NUM_NEURONS / 2)     // 32768 float2 lanes
#define THREADS     32                    // 1 warp per block
#define BLOCKS      (NVEC / THREADS)      // 1024 blocks
#define STAGES      5                     // timesteps per pipeline block (200 blocks)

__device__ __forceinline__ float2 lif_step(const float2 i2, const float2 n2,
                                           float2& V, float2& th)
{
    const float decay = 0.05f, eta = 0.1f, nstd = 0.1f;
    const float thmin = 0.5f, thmax = 2.0f;
    float2 s;
#define LIF_C(c)                                                     \
    {                                                                \
        float ie = fmaf(nstd, n2.c, i2.c);                           \
        float v  = fmaf(decay, ie - V.c, V.c);                       \
        bool  sp = (v >= th.c);                                      \
        s.c  = sp ? 1.0f : 0.0f;                                     \
        V.c  = sp ? 0.0f : v;                                        \
        th.c = fminf(fmaxf(fmaf(eta, s.c, th.c), thmin), thmax);     \
    }
    LIF_C(x) LIF_C(y)
#undef LIF_C
    return s;
}

__global__ __launch_bounds__(THREADS, 7)
void lif_kernel(const float2* __restrict__ icur,
                const float2* __restrict__ nz,
                float2* __restrict__ out)
{
    const int idx = blockIdx.x * THREADS + threadIdx.x;   // 0 .. NVEC-1

    const float2* ip = icur + idx;
    const float2* np = nz   + idx;
    float2*       op = out  + idx;

    float2 V  = make_float2(0.0f, 0.0f);
    float2 th = make_float2(1.0f, 1.0f);

    float2 AI[STAGES], AN[STAGES];
    float2 BI[STAGES], BN[STAGES];
    float2 CI[STAGES], CN[STAGES];
    float2 DI[STAGES], DN[STAGES];
    float2 EI[STAGES], EN[STAGES];
    float2 FI[STAGES], FN[STAGES];
    float2 GI[STAGES], GN[STAGES];
    float2 HI[STAGES], HN[STAGES];

    // blk b covers timesteps [b*STAGES, (b+1)*STAGES)
#define LOAD_BLK(I_, N_, b)                                           \
    _Pragma("unroll")                                                 \
    for (int j = 0; j < STAGES; j++) {                                \
        I_[j] = __ldcs(ip + (size_t)((b) * STAGES + j) * NVEC);       \
        N_[j] = __ldcs(np + (size_t)((b) * STAGES + j) * NVEC);      \
    }

    // default write-back store (the single change vs R8)
#define COMP_BLK(I_, N_, b)                                           \
    _Pragma("unroll")                                                 \
    for (int j = 0; j < STAGES; j++) {                                \
        float2 s = lif_step(I_[j], N_[j], V, th);                     \
        op[(size_t)((b) * STAGES + j) * NVEC] = s;                    \
    }

    // 200 blocks of 5. Eight rotating buffers: loads run 7 blocks ahead.
    LOAD_BLK(AI, AN, 0)
    LOAD_BLK(BI, BN, 1)
    LOAD_BLK(CI, CN, 2)
    LOAD_BLK(DI, DN, 3)
    LOAD_BLK(EI, EN, 4)
    LOAD_BLK(FI, FN, 5)
    LOAD_BLK(GI, GN, 6)

    for (int p = 0; p < 24; p++) {
        const int b = 8 * p;                                 // 0,8,...,184
        LOAD_BLK(HI, HN, b + 7)    COMP_BLK(AI, AN, b)       // load <= 191
        LOAD_BLK(AI, AN, b + 8)    COMP_BLK(BI, BN, b + 1)   // load <= 192
        LOAD_BLK(BI, BN, b + 9)    COMP_BLK(CI, CN, b + 2)   // load <= 193
        LOAD_BLK(CI, CN, b + 10)   COMP_BLK(DI, DN, b + 3)   // load <= 194
        LOAD_BLK(DI, DN, b + 11)   COMP_BLK(EI, EN, b + 4)   // load <= 195
        LOAD_BLK(EI, EN, b + 12)   COMP_BLK(FI, FN, b + 5)   // load <= 196
        LOAD_BLK(FI, FN, b + 13)   COMP_BLK(GI, GN, b + 6)   // load <= 197
        LOAD_BLK(GI, GN, b + 14)   COMP_BLK(HI, HN, b + 7)   // load <= 198
    }
    // computed 0..191; A=192, B=193, C=194, D=195, E=196, F=197, G=198
    LOAD_BLK(HI, HN, 199)   COMP_BLK(AI, AN, 192)
    COMP_BLK(BI, BN, 193)
    COMP_BLK(CI, CN, 194)
    COMP_BLK(DI, DN, 195)
    COMP_BLK(EI, EN, 196)
    COMP_BLK(FI, FN, 197)
    COMP_BLK(GI, GN, 198)
    COMP_BLK(HI, HN, 199)

#undef LOAD_BLK
#undef COMP_BLK
}

extern "C" void kernel_launch(void* const* d_in, const int* in_sizes, int n_in,
                              void* d_out, int out_size)
{
    const float2* icur = (const float2*)d_in[0];   // input_current (T, N) f32
    const float2* nz   = (const float2*)d_in[1];   // noise         (T, N) f32
    float2*       out  = (float2*)d_out;           // spikes        (T, N) f32

    lif_kernel<<<BLOCKS, THREADS>>>(icur, nz, out);
}

// round 10
// speedup vs baseline: 1.0090x; 1.0090x over previous
#include <cuda_runtime.h>

// LIF neuron group, T=1000 serial steps x 65536 neurons. Pure HBM stream
// (512 MB read + 256 MB write, irreducible). Converged pipeline structure
// (R5/R6/R8 all ~6.6 TB/s): float2 lanes, 1024 one-warp blocks (7-vs-6 per
// SM), 8 rotating register buffers x STAGES=5, loads 7 blocks ahead, .cs
// loads. Store-policy A/B history: .cs = 83.4% DRAM, write-back = 79.9%
// (R9, L2 dirty-eviction interferes with reads). R10 tests the last point
// on this axis: write-through (__stwt) — no L2 dirty line at all, write
// batching happens in the memory controller's write queue instead.

#define NUM_NEURONS 65536
#define T_STEPS     1000
#define NVEC        (NUM_NEURONS / 2)     // 32768 float2 lanes
#define THREADS     32                    // 1 warp per block
#define BLOCKS      (NVEC / THREADS)      // 1024 blocks
#define STAGES      5                     // timesteps per pipeline block (200 blocks)

__device__ __forceinline__ float2 lif_step(const float2 i2, const float2 n2,
                                           float2& V, float2& th)
{
    const float decay = 0.05f, eta = 0.1f, nstd = 0.1f;
    const float thmin = 0.5f, thmax = 2.0f;
    float2 s;
#define LIF_C(c)                                                     \
    {                                                                \
        float ie = fmaf(nstd, n2.c, i2.c);                           \
        float v  = fmaf(decay, ie - V.c, V.c);                       \
        bool  sp = (v >= th.c);                                      \
        s.c  = sp ? 1.0f : 0.0f;                                     \
        V.c  = sp ? 0.0f : v;                                        \
        th.c = fminf(fmaxf(fmaf(eta, s.c, th.c), thmin), thmax);     \
    }
    LIF_C(x) LIF_C(y)
#undef LIF_C
    return s;
}

__global__ __launch_bounds__(THREADS, 7)
void lif_kernel(const float2* __restrict__ icur,
                const float2* __restrict__ nz,
                float2* __restrict__ out)
{
    const int idx = blockIdx.x * THREADS + threadIdx.x;   // 0 .. NVEC-1

    const float2* ip = icur + idx;
    const float2* np = nz   + idx;
    float2*       op = out  + idx;

    float2 V  = make_float2(0.0f, 0.0f);
    float2 th = make_float2(1.0f, 1.0f);

    float2 AI[STAGES], AN[STAGES];
    float2 BI[STAGES], BN[STAGES];
    float2 CI[STAGES], CN[STAGES];
    float2 DI[STAGES], DN[STAGES];
    float2 EI[STAGES], EN[STAGES];
    float2 FI[STAGES], FN[STAGES];
    float2 GI[STAGES], GN[STAGES];
    float2 HI[STAGES], HN[STAGES];

    // blk b covers timesteps [b*STAGES, (b+1)*STAGES)
#define LOAD_BLK(I_, N_, b)                                           \
    _Pragma("unroll")                                                 \
    for (int j = 0; j < STAGES; j++) {                                \
        I_[j] = __ldcs(ip + (size_t)((b) * STAGES + j) * NVEC);       \
        N_[j] = __ldcs(np + (size_t)((b) * STAGES + j) * NVEC);      \
    }

    // write-through store (the single change vs the R8 champion)
#define COMP_BLK(I_, N_, b)                                           \
    _Pragma("unroll")                                                 \
    for (int j = 0; j < STAGES; j++) {                                \
        float2 s = lif_step(I_[j], N_[j], V, th);                     \
        __stwt(op + (size_t)((b) * STAGES + j) * NVEC, s);            \
    }

    // 200 blocks of 5. Eight rotating buffers: loads run 7 blocks ahead.
    LOAD_BLK(AI, AN, 0)
    LOAD_BLK(BI, BN, 1)
    LOAD_BLK(CI, CN, 2)
    LOAD_BLK(DI, DN, 3)
    LOAD_BLK(EI, EN, 4)
    LOAD_BLK(FI, FN, 5)
    LOAD_BLK(GI, GN, 6)

    for (int p = 0; p < 24; p++) {
        const int b = 8 * p;                                 // 0,8,...,184
        LOAD_BLK(HI, HN, b + 7)    COMP_BLK(AI, AN, b)       // load <= 191
        LOAD_BLK(AI, AN, b + 8)    COMP_BLK(BI, BN, b + 1)   // load <= 192
        LOAD_BLK(BI, BN, b + 9)    COMP_BLK(CI, CN, b + 2)   // load <= 193
        LOAD_BLK(CI, CN, b + 10)   COMP_BLK(DI, DN, b + 3)   // load <= 194
        LOAD_BLK(DI, DN, b + 11)   COMP_BLK(EI, EN, b + 4)   // load <= 195
        LOAD_BLK(EI, EN, b + 12)   COMP_BLK(FI, FN, b + 5)   // load <= 196
        LOAD_BLK(FI, FN, b + 13)   COMP_BLK(GI, GN, b + 6)   // load <= 197
        LOAD_BLK(GI, GN, b + 14)   COMP_BLK(HI, HN, b + 7)   // load <= 198
    }
    // computed 0..191; A=192, B=193, C=194, D=195, E=196, F=197, G=198
    LOAD_BLK(HI, HN, 199)   COMP_BLK(AI, AN, 192)
    COMP_BLK(BI, BN, 193)
    COMP_BLK(CI, CN, 194)
    COMP_BLK(DI, DN, 195)
    COMP_BLK(EI, EN, 196)
    COMP_BLK(FI, FN, 197)
    COMP_BLK(GI, GN, 198)
    COMP_BLK(HI, HN, 199)

#undef LOAD_BLK
#undef COMP_BLK
}

extern "C" void kernel_launch(void* const* d_in, const int* in_sizes, int n_in,
                              void* d_out, int out_size)
{
    const float2* icur = (const float2*)d_in[0];   // input_current (T, N) f32
    const float2* nz   = (const float2*)d_in[1];   // noise         (T, N) f32
    float2*       out  = (float2*)d_out;           // spikes        (T, N) f32

    lif_kernel<<<BLOCKS, THREADS>>>(icur, nz, out);
}

// round 11
// speedup vs baseline: 1.0437x; 1.0344x over previous
#include <cuda_runtime.h>

// LIF neuron group, T=1000 serial steps x 65536 neurons. Pure HBM stream
// (512 MB read + 256 MB write, irreducible). Converged structure = R6
// champion: float2 lanes, 1024 one-warp blocks (7-vs-6 per SM), quint
// rotating register buffers x STAGES=8 (loads 4 blocks ahead, ~17 MB
// chip-wide in flight), .cs stores (store-policy axis mapped: .cs 83.4% >
// .wt 81.1% > WB 79.9% DRAM-active).
// R11 single-variable test: loads .cs -> .cg (__ldcg, L2-only, bypass L1
// fill). Data is never re-read; skipping the L1 line allocation removes
// l1tex fill work from the return path of ~140 in-flight loads/warp.

#define NUM_NEURONS 65536
#define T_STEPS     1000
#define NVEC        (NUM_NEURONS / 2)     // 32768 float2 lanes
#define THREADS     32                    // 1 warp per block
#define BLOCKS      (NVEC / THREADS)      // 1024 blocks
#define STAGES      8                     // timesteps per pipeline block (125 blocks)

__device__ __forceinline__ float2 lif_step(const float2 i2, const float2 n2,
                                           float2& V, float2& th)
{
    const float decay = 0.05f, eta = 0.1f, nstd = 0.1f;
    const float thmin = 0.5f, thmax = 2.0f;
    float2 s;
#define LIF_C(c)                                                     \
    {                                                                \
        float ie = fmaf(nstd, n2.c, i2.c);                           \
        float v  = fmaf(decay, ie - V.c, V.c);                       \
        bool  sp = (v >= th.c);                                      \
        s.c  = sp ? 1.0f : 0.0f;                                     \
        V.c  = sp ? 0.0f : v;                                        \
        th.c = fminf(fmaxf(fmaf(eta, s.c, th.c), thmin), thmax);     \
    }
    LIF_C(x) LIF_C(y)
#undef LIF_C
    return s;
}

__global__ __launch_bounds__(THREADS, 7)
void lif_kernel(const float2* __restrict__ icur,
                const float2* __restrict__ nz,
                float2* __restrict__ out)
{
    const int idx = blockIdx.x * THREADS + threadIdx.x;   // 0 .. NVEC-1

    const float2* ip = icur + idx;
    const float2* np = nz   + idx;
    float2*       op = out  + idx;

    float2 V  = make_float2(0.0f, 0.0f);
    float2 th = make_float2(1.0f, 1.0f);

    float2 AI[STAGES], AN[STAGES];
    float2 BI[STAGES], BN[STAGES];
    float2 CI[STAGES], CN[STAGES];
    float2 DI[STAGES], DN[STAGES];
    float2 EI[STAGES], EN[STAGES];

    // blk b covers timesteps [b*STAGES, (b+1)*STAGES)
#define LOAD_BLK(I_, N_, b)                                           \
    _Pragma("unroll")                                                 \
    for (int j = 0; j < STAGES; j++) {                                \
        I_[j] = __ldcg(ip + (size_t)((b) * STAGES + j) * NVEC);       \
        N_[j] = __ldcg(np + (size_t)((b) * STAGES + j) * NVEC);      \
    }

#define COMP_BLK(I_, N_, b)                                           \
    _Pragma("unroll")                                                 \
    for (int j = 0; j < STAGES; j++) {                                \
        float2 s = lif_step(I_[j], N_[j], V, th);                     \
        __stcs(op + (size_t)((b) * STAGES + j) * NVEC, s);            \
    }

    // 125 blocks of 8. Quint buffer: loads run 4 blocks ahead of compute.
    LOAD_BLK(AI, AN, 0)
    LOAD_BLK(BI, BN, 1)
    LOAD_BLK(CI, CN, 2)
    LOAD_BLK(DI, DN, 3)

    for (int p = 0; p < 24; p++) {
        const int b = 5 * p;                                 // 0,5,...,115
        LOAD_BLK(EI, EN, b + 4)   COMP_BLK(AI, AN, b)        // load <= 119
        LOAD_BLK(AI, AN, b + 5)   COMP_BLK(BI, BN, b + 1)    // load <= 120
        LOAD_BLK(BI, BN, b + 6)   COMP_BLK(CI, CN, b + 2)    // load <= 121
        LOAD_BLK(CI, CN, b + 7)   COMP_BLK(DI, DN, b + 3)    // load <= 122
        LOAD_BLK(DI, DN, b + 8)   COMP_BLK(EI, EN, b + 4)    // load <= 123
    }
    // computed 0..119; A=120, B=121, C=122, D=123
    LOAD_BLK(EI, EN, 124)   COMP_BLK(AI, AN, 120)
    COMP_BLK(BI, BN, 121)
    COMP_BLK(CI, CN, 122)
    COMP_BLK(DI, DN, 123)
    COMP_BLK(EI, EN, 124)

#undef LOAD_BLK
#undef COMP_BLK
}

extern "C" void kernel_launch(void* const* d_in, const int* in_sizes, int n_in,
                              void* d_out, int out_size)
{
    const float2* icur = (const float2*)d_in[0];   // input_current (T, N) f32
    const float2* nz   = (const float2*)d_in[1];   // noise         (T, N) f32
    float2*       out  = (float2*)d_out;           // spikes        (T, N) f32

    lif_kernel<<<BLOCKS, THREADS>>>(icur, nz, out);
}